// round 15
// baseline (speedup 1.0000x reference)
#include <cuda_runtime.h>
#include <cuda_fp16.h>
#include <math.h>
#include <stdint.h>

#define NN 100000
#define EE 1600000
#define GG 1000
#define HH 64
#define CC 10
#define CAP 64      // per-node bucket capacity (deg ~ Poisson(16); P(>64) ~ 0)
#define BN_EPS 1e-5f
#define NSLOT 16    // BN stat shards (kills same-address REDG serialization)
#define SP 66       // padded smem row stride in halves (33 words -> conflict-free)

// ---------------- scratch (static device memory; no allocation at runtime) ----
__device__ __align__(16) int    g_cnt[NN];             // in-degree (excl self loop)
__device__ __align__(16) int    g_srcs[NN * CAP];      // bucketized CSR (padded to 8 with NN)
__device__ __align__(16) __half g_t[(NN + 1) * HH];    // dis-scaled features; row NN = zeros
__device__ __align__(16) float  g_h[NN * HH];          // conv1 output
__device__ __align__(16) float  g_bnp[NSLOT * 128];    // sharded BN sums
__device__ __align__(16) float  g_cbn[128];
__device__ __align__(16) float  g_gsum[GG * HH];
__device__ __align__(16) float  g_gcnt[GG];
__device__ __align__(16) float  g_z1[GG * HH];

// PDL: wait for upstream grid's memory to be visible
__device__ __forceinline__ void gds() {
#if defined(__CUDA_ARCH__) && __CUDA_ARCH__ >= 900
    cudaGridDependencySynchronize();
#endif
}

// ---------------- zero scratch ------------------------------------------------
__global__ void k_zero() {
    gds();   // don't race previous replay's tail kernels
    int i = blockIdx.x * blockDim.x + threadIdx.x;
    if (i < NN) g_cnt[i] = 0;
    if (i < NSLOT * 128) g_bnp[i] = 0.f;
    if (i < 128) g_cbn[i] = 0.f;
    if (i < GG * HH) g_gsum[i] = 0.f;
    if (i < GG) g_gcnt[i] = 0.f;
    if (i < 32) ((uint32_t*)g_t)[NN * 32 + i] = 0;   // sentinel row = zeros
}

// ------- single-pass bucket fill: 4 edges per thread (int4 loads) -------------
__global__ void k_fill(const int* __restrict__ ei) {
    int i = blockIdx.x * blockDim.x + threadIdx.x;
    if (i >= EE / 4) return;
    gds();
    int4 s = ((const int4*)ei)[i];
    int4 d = ((const int4*)(ei + EE))[i];
    int p;
    p = atomicAdd(&g_cnt[d.x], 1); if (p < CAP) g_srcs[d.x * CAP + p] = s.x;
    p = atomicAdd(&g_cnt[d.y], 1); if (p < CAP) g_srcs[d.y * CAP + p] = s.y;
    p = atomicAdd(&g_cnt[d.z], 1); if (p < CAP) g_srcs[d.z * CAP + p] = s.z;
    p = atomicAdd(&g_cnt[d.w], 1); if (p < CAP) g_srcs[d.w * CAP + p] = s.w;
}

// ---- tensor-core transform: g_t = dis[r] * ([BN+ReLU](src[r]) @ W + b) -------
// Also pads each covered bucket row to a multiple of 8 with sentinel NN.
template <int MODE>
__global__ void k_gemm(const float* __restrict__ in, const float* __restrict__ W,
                       const float* __restrict__ bias,
                       const float* __restrict__ gamma, const float* __restrict__ beta) {
    __shared__ __half xs[128 * SP];   // per-warp 16-row staging (fp16)
    __shared__ __half wt[64 * SP];    // W^T: wt[n][k]
    __shared__ float  bsh[64];
    __shared__ float  bnred[128];     // reduced BN sums (MODE 1)
    int tid = threadIdx.x;
    int warp = tid >> 5, lane = tid & 31;

    for (int i = tid; i < 4096; i += 256) {
        int n = i >> 6, k = i & 63;
        wt[n * SP + k] = __float2half(W[k * 64 + n]);
    }
    if (tid < 64) bsh[tid] = bias[tid];

    gds();   // upstream (fill / aggregate) results now visible

    // pad bucket rows to 8-multiple with sentinel (needs g_cnt from fill)
    if (tid < 128) {
        int pr = blockIdx.x * 128 + tid;
        if (pr < NN) {
            int d = g_cnt[pr];
            if (d < CAP) {
                int dp = (d + 7) & ~7;
                if (dp > CAP) dp = CAP;
                for (int j = d; j < dp; j++) g_srcs[pr * CAP + j] = NN;
            }
        }
    }

    // MODE 1: reduce the 16 BN shards into smem
    if (MODE == 1 && tid < 128) {
        float s = 0.f;
        #pragma unroll
        for (int j = 0; j < NSLOT; j++) s += g_bnp[j * 128 + tid];
        bnred[tid] = s;
    }
    __syncthreads();

    int c0 = 2 * lane, c1 = c0 + 1;
    float a0 = 1.f, s0 = 0.f, a1 = 1.f, s1 = 0.f;
    if (MODE == 1) {
        const float invn = 1.0f / NN;
        float mu0 = bnred[c0] * invn, mu1 = bnred[c1] * invn;
        float var0 = bnred[64 + c0] * invn - mu0 * mu0;
        float var1 = bnred[64 + c1] * invn - mu1 * mu1;
        a0 = rsqrtf(var0 + BN_EPS) * gamma[c0];
        a1 = rsqrtf(var1 + BN_EPS) * gamma[c1];
        s0 = beta[c0] - mu0 * a0;
        s1 = beta[c1] - mu1 * a1;
    }

    int wrow0 = blockIdx.x * 128 + warp * 16;   // NN % 16 == 0
    if (wrow0 >= NN) return;

    const float* __restrict__ src = (MODE == 1) ? (const float*)g_h : in;
    __half* xw = xs + warp * 16 * SP;

    #pragma unroll
    for (int r = 0; r < 16; r++) {
        float2 v = *(const float2*)(src + (size_t)(wrow0 + r) * 64 + c0);
        if (MODE == 1) {
            v.x = fmaxf(fmaf(v.x, a0, s0), 0.f);
            v.y = fmaxf(fmaf(v.y, a1, s1), 0.f);
        }
        *(__half2*)&xw[r * SP + c0] = __floats2half2_rn(v.x, v.y);
    }
    __syncwarp();

    int gr = lane >> 2, tg = lane & 3;
    float acc[8][4];
    #pragma unroll
    for (int nt = 0; nt < 8; nt++) {
        float bx = bsh[nt * 8 + tg * 2], by = bsh[nt * 8 + tg * 2 + 1];
        acc[nt][0] = bx; acc[nt][1] = by; acc[nt][2] = bx; acc[nt][3] = by;
    }
    #pragma unroll
    for (int ks = 0; ks < 4; ks++) {
        int kb = ks * 16 + tg * 2;
        uint32_t fa0 = *(const uint32_t*)&xw[gr * SP + kb];
        uint32_t fa1 = *(const uint32_t*)&xw[(gr + 8) * SP + kb];
        uint32_t fa2 = *(const uint32_t*)&xw[gr * SP + kb + 8];
        uint32_t fa3 = *(const uint32_t*)&xw[(gr + 8) * SP + kb + 8];
        #pragma unroll
        for (int nt = 0; nt < 8; nt++) {
            uint32_t fb0 = *(const uint32_t*)&wt[(nt * 8 + gr) * SP + kb];
            uint32_t fb1 = *(const uint32_t*)&wt[(nt * 8 + gr) * SP + kb + 8];
            asm volatile(
                "mma.sync.aligned.m16n8k16.row.col.f32.f16.f16.f32 "
                "{%0,%1,%2,%3}, {%4,%5,%6,%7}, {%8,%9}, {%0,%1,%2,%3};"
                : "+f"(acc[nt][0]), "+f"(acc[nt][1]), "+f"(acc[nt][2]), "+f"(acc[nt][3])
                : "r"(fa0), "r"(fa1), "r"(fa2), "r"(fa3), "r"(fb0), "r"(fb1));
        }
    }
    float dv0 = rsqrtf((float)(g_cnt[wrow0 + gr] + 1));
    float dv8 = rsqrtf((float)(g_cnt[wrow0 + gr + 8] + 1));
    __syncwarp();
    #pragma unroll
    for (int nt = 0; nt < 8; nt++) {
        int cc = nt * 8 + tg * 2;
        *(__half2*)&xw[gr * SP + cc]       = __floats2half2_rn(acc[nt][0] * dv0, acc[nt][1] * dv0);
        *(__half2*)&xw[(gr + 8) * SP + cc] = __floats2half2_rn(acc[nt][2] * dv8, acc[nt][3] * dv8);
    }
    __syncwarp();
    uint32_t* gw = (uint32_t*)g_t;
    #pragma unroll
    for (int r = 0; r < 16; r++) {
        gw[(size_t)(wrow0 + r) * 32 + lane] = ((const uint32_t*)&xw[r * SP])[lane];
    }
}

// ---- aggregate, TWO nodes per warp (interleaved independent chains) ----------
// lanes 0-15 get cols [4q..4q+3]; 2 edges per LDG.64; 8 edges/node/iteration.
__device__ __forceinline__ void agg_pair(int v0, int v1, int lane,
                                         float fa[4], float fb[4]) {
    int deg0 = g_cnt[v0], deg1 = g_cnt[v1];
    int degp0 = (min(deg0, CAP) + 7) & ~7;
    int degp1 = (min(deg1, CAP) + 7) & ~7;
    int half = lane >> 4, q = lane & 15;
    const int* __restrict__ r0 = g_srcs + (size_t)v0 * CAP;
    const int* __restrict__ r1 = g_srcs + (size_t)v1 * CAP;
    const __half* __restrict__ t = g_t;
    float a0 = 0.f, a1 = 0.f, a2 = 0.f, a3 = 0.f;
    float b0 = 0.f, b1 = 0.f, b2 = 0.f, b3 = 0.f;
    int emax = max(degp0, degp1);
    for (int e = 0; e < emax; e += 8) {
        if (e < degp0) {
            int4 i0 = *(const int4*)(r0 + e);
            int4 i1 = *(const int4*)(r0 + e + 4);
            int sa0 = half ? i0.y : i0.x, sb0 = half ? i0.w : i0.z;
            int sa1 = half ? i1.y : i1.x, sb1 = half ? i1.w : i1.z;
            uint2 u0 = __ldcg((const uint2*)(t + (size_t)sa0 * 64) + q);
            uint2 u1 = __ldcg((const uint2*)(t + (size_t)sb0 * 64) + q);
            uint2 u2 = __ldcg((const uint2*)(t + (size_t)sa1 * 64) + q);
            uint2 u3 = __ldcg((const uint2*)(t + (size_t)sb1 * 64) + q);
            __half2 h0 = __hadd2(__hadd2(*(__half2*)&u0.x, *(__half2*)&u1.x),
                                 __hadd2(*(__half2*)&u2.x, *(__half2*)&u3.x));
            __half2 h1 = __hadd2(__hadd2(*(__half2*)&u0.y, *(__half2*)&u1.y),
                                 __hadd2(*(__half2*)&u2.y, *(__half2*)&u3.y));
            float2 p = __half22float2(h0);
            float2 r = __half22float2(h1);
            a0 += p.x; a1 += p.y; a2 += r.x; a3 += r.y;
        }
        if (e < degp1) {
            int4 i0 = *(const int4*)(r1 + e);
            int4 i1 = *(const int4*)(r1 + e + 4);
            int sa0 = half ? i0.y : i0.x, sb0 = half ? i0.w : i0.z;
            int sa1 = half ? i1.y : i1.x, sb1 = half ? i1.w : i1.z;
            uint2 u0 = __ldcg((const uint2*)(t + (size_t)sa0 * 64) + q);
            uint2 u1 = __ldcg((const uint2*)(t + (size_t)sb0 * 64) + q);
            uint2 u2 = __ldcg((const uint2*)(t + (size_t)sa1 * 64) + q);
            uint2 u3 = __ldcg((const uint2*)(t + (size_t)sb1 * 64) + q);
            __half2 h0 = __hadd2(__hadd2(*(__half2*)&u0.x, *(__half2*)&u1.x),
                                 __hadd2(*(__half2*)&u2.x, *(__half2*)&u3.x));
            __half2 h1 = __hadd2(__hadd2(*(__half2*)&u0.y, *(__half2*)&u1.y),
                                 __hadd2(*(__half2*)&u2.y, *(__half2*)&u3.y));
            float2 p = __half22float2(h0);
            float2 r = __half22float2(h1);
            b0 += p.x; b1 += p.y; b2 += r.x; b3 += r.y;
        }
    }
    // combine half-warps (lanes 0-15 get totals)
    a0 += __shfl_down_sync(0xffffffff, a0, 16);
    a1 += __shfl_down_sync(0xffffffff, a1, 16);
    a2 += __shfl_down_sync(0xffffffff, a2, 16);
    a3 += __shfl_down_sync(0xffffffff, a3, 16);
    b0 += __shfl_down_sync(0xffffffff, b0, 16);
    b1 += __shfl_down_sync(0xffffffff, b1, 16);
    b2 += __shfl_down_sync(0xffffffff, b2, 16);
    b3 += __shfl_down_sync(0xffffffff, b3, 16);
    // self terms + normalization
    uint2 us0 = ((const uint2*)(t + (size_t)v0 * 64))[q];
    uint2 us1 = ((const uint2*)(t + (size_t)v1 * 64))[q];
    float2 s0a = __half22float2(*(__half2*)&us0.x);
    float2 s0b = __half22float2(*(__half2*)&us0.y);
    float2 s1a = __half22float2(*(__half2*)&us1.x);
    float2 s1b = __half22float2(*(__half2*)&us1.y);
    float dv0 = rsqrtf((float)(deg0 + 1));
    float dv1 = rsqrtf((float)(deg1 + 1));
    fa[0] = (a0 + s0a.x) * dv0;  fa[1] = (a1 + s0a.y) * dv0;
    fa[2] = (a2 + s0b.x) * dv0;  fa[3] = (a3 + s0b.y) * dv0;
    fb[0] = (b0 + s1a.x) * dv1;  fb[1] = (b1 + s1a.y) * dv1;
    fb[2] = (b2 + s1b.x) * dv1;  fb[3] = (b3 + s1b.y) * dv1;
}

// conv1 aggregate: 16 nodes/block, write g_h + sharded BN stats. NN%16==0.
__global__ void __launch_bounds__(256) k_agg_bnstats() {
    __shared__ __align__(16) float ssum[16][64];
    __shared__ __align__(16) float ssq[16][64];
    gds();
    int tid = threadIdx.x;
    int warp = tid >> 5, lane = tid & 31;
    int q = lane & 15;
    int v0 = blockIdx.x * 16 + warp * 2;
    float fa[4], fb[4];
    agg_pair(v0, v0 + 1, lane, fa, fb);
    if (lane < 16) {
        *(float4*)(g_h + (size_t)v0 * 64 + q * 4) = make_float4(fa[0], fa[1], fa[2], fa[3]);
        *(float4*)(g_h + (size_t)(v0 + 1) * 64 + q * 4) = make_float4(fb[0], fb[1], fb[2], fb[3]);
        *(float4*)&ssum[warp * 2][q * 4]     = make_float4(fa[0], fa[1], fa[2], fa[3]);
        *(float4*)&ssum[warp * 2 + 1][q * 4] = make_float4(fb[0], fb[1], fb[2], fb[3]);
        *(float4*)&ssq[warp * 2][q * 4]      = make_float4(fa[0]*fa[0], fa[1]*fa[1], fa[2]*fa[2], fa[3]*fa[3]);
        *(float4*)&ssq[warp * 2 + 1][q * 4]  = make_float4(fb[0]*fb[0], fb[1]*fb[1], fb[2]*fb[2], fb[3]*fb[3]);
    }
    __syncthreads();
    float* slot = g_bnp + (blockIdx.x & (NSLOT - 1)) * 128;
    if (tid < 64) {
        float s = 0.f, qq = 0.f;
        #pragma unroll
        for (int w = 0; w < 16; w++) { s += ssum[w][tid]; qq += ssq[w][tid]; }
        atomicAdd(&slot[tid], s);
        atomicAdd(&slot[64 + tid], qq);
    }
}

// conv2 aggregate fused with per-graph mean pooling (batch sorted -> run dedup)
__global__ void __launch_bounds__(256) k_agg_pool(const int* __restrict__ batch) {
    __shared__ __align__(16) float vals[16][64];
    __shared__ int gids[16];
    gds();
    int tid = threadIdx.x;
    int warp = tid >> 5, lane = tid & 31;
    int q = lane & 15;
    int v0 = blockIdx.x * 16 + warp * 2;
    float fa[4], fb[4];
    agg_pair(v0, v0 + 1, lane, fa, fb);
    if (lane < 16) {
        *(float4*)&vals[warp * 2][q * 4]     = make_float4(fa[0], fa[1], fa[2], fa[3]);
        *(float4*)&vals[warp * 2 + 1][q * 4] = make_float4(fb[0], fb[1], fb[2], fb[3]);
    }
    if (lane == 0) {
        gids[warp * 2] = batch[v0];
        gids[warp * 2 + 1] = batch[v0 + 1];
    }
    __syncthreads();
    if (tid < 64) {
        int c = tid;
        float acc = 0.f;
        int cur = -1;
        #pragma unroll
        for (int w = 0; w < 16; w++) {
            int gw = gids[w];
            if (gw != cur) {
                if (cur >= 0) atomicAdd(&g_gsum[cur * 64 + c], acc);
                cur = gw;
                acc = 0.f;
            }
            acc += vals[w][c];
        }
        if (cur >= 0) atomicAdd(&g_gsum[cur * 64 + c], acc);
    } else if (tid == 64) {
        float cnt = 0.f;
        int cur = -1;
        #pragma unroll
        for (int w = 0; w < 16; w++) {
            int gw = gids[w];
            if (gw != cur) {
                if (cur >= 0) atomicAdd(&g_gcnt[cur], cnt);
                cur = gw;
                cnt = 0.f;
            }
            cnt += 1.f;
        }
        if (cur >= 0) atomicAdd(&g_gcnt[cur], cnt);
    }
}

// ---------------- graph-level: pool finalize + L2 norm + Wc1 ------------------
__global__ void k_graph1(const float* __restrict__ Wc1, const float* __restrict__ bc1,
                         float* __restrict__ rep_out) {
    __shared__ __align__(16) float Wsh[64 * 64];
    __shared__ float bsh[64];
    __shared__ float xsh[8][64];
    int tid = threadIdx.x;
    for (int i = tid; i < 4096; i += 256) Wsh[i] = Wc1[i];
    if (tid < 64) bsh[tid] = bc1[tid];
    gds();
    __syncthreads();
    int warp = tid >> 5, lane = tid & 31;
    int g = blockIdx.x * 8 + warp;
    if (g >= GG) return;
    float cnt = fmaxf(g_gcnt[g], 1.0f);
    float mx = g_gsum[g * 64 + 2 * lane] / cnt;
    float my = g_gsum[g * 64 + 2 * lane + 1] / cnt;
    float ss = mx * mx + my * my;
    #pragma unroll
    for (int o = 16; o > 0; o >>= 1) ss += __shfl_xor_sync(0xffffffff, ss, o);
    float inv = rsqrtf(ss);
    mx *= inv; my *= inv;
    rep_out[g * 64 + 2 * lane] = mx;
    rep_out[g * 64 + 2 * lane + 1] = my;
    xsh[warp][2 * lane] = mx;
    xsh[warp][2 * lane + 1] = my;
    __syncwarp();
    float ax = bsh[2 * lane], ay = bsh[2 * lane + 1];
    #pragma unroll
    for (int k = 0; k < 64; k++) {
        float xk = xsh[warp][k];
        float2 w = *(const float2*)&Wsh[k * 64 + 2 * lane];
        ax += xk * w.x;
        ay += xk * w.y;
    }
    g_z1[g * 64 + 2 * lane] = ax;
    g_z1[g * 64 + 2 * lane + 1] = ay;
    atomicAdd(&g_cbn[2 * lane], ax);
    atomicAdd(&g_cbn[2 * lane + 1], ay);
    atomicAdd(&g_cbn[64 + 2 * lane], ax * ax);
    atomicAdd(&g_cbn[64 + 2 * lane + 1], ay * ay);
}

// ---- classifier tail: BN(finalized in-kernel)+ReLU -> Wc2 -> log_softmax -----
__global__ void k_graph2(const float* __restrict__ Wc2, const float* __restrict__ bc2,
                         const float* __restrict__ gammac, const float* __restrict__ betac,
                         float* __restrict__ pred_out) {
    __shared__ float Wsh[64 * 10];
    __shared__ float xsh[8][64];
    int tid = threadIdx.x;
    for (int i = tid; i < 640; i += 256) Wsh[i] = Wc2[i];
    gds();
    __syncthreads();
    int warp = tid >> 5, lane = tid & 31;
    int g = blockIdx.x * 8 + warp;
    if (g >= GG) return;
    int c0 = 2 * lane, c1 = 2 * lane + 1;
    const float invg = 1.0f / GG;
    float mu0 = g_cbn[c0] * invg, mu1 = g_cbn[c1] * invg;
    float var0 = g_cbn[64 + c0] * invg - mu0 * mu0;
    float var1 = g_cbn[64 + c1] * invg - mu1 * mu1;
    float is0 = rsqrtf(var0 + BN_EPS), is1 = rsqrtf(var1 + BN_EPS);
    float z0 = g_z1[g * 64 + c0];
    float z1v = g_z1[g * 64 + c1];
    z0 = fmaxf((z0 - mu0) * is0 * gammac[c0] + betac[c0], 0.f);
    z1v = fmaxf((z1v - mu1) * is1 * gammac[c1] + betac[c1], 0.f);
    xsh[warp][c0] = z0;
    xsh[warp][c1] = z1v;
    __syncwarp();
    bool valid = (lane < CC);
    float acc = valid ? bc2[lane] : 0.f;
    if (valid) {
        #pragma unroll
        for (int k = 0; k < 64; k++) acc += xsh[warp][k] * Wsh[k * 10 + lane];
    }
    float v = valid ? acc : -1e30f;
    float m = v;
    #pragma unroll
    for (int o = 16; o > 0; o >>= 1) m = fmaxf(m, __shfl_xor_sync(0xffffffff, m, o));
    float ex = valid ? __expf(v - m) : 0.f;
    float s = ex;
    #pragma unroll
    for (int o = 16; o > 0; o >>= 1) s += __shfl_xor_sync(0xffffffff, s, o);
    if (valid) pred_out[g * CC + lane] = v - m - logf(s);
}

// ---------------- PDL launcher ------------------------------------------------
template <typename... Args>
static inline void pdl_launch(void (*kern)(Args...), dim3 grid, dim3 block, Args... args) {
    cudaLaunchConfig_t cfg = {};
    cfg.gridDim = grid;
    cfg.blockDim = block;
    cfg.dynamicSmemBytes = 0;
    cfg.stream = 0;
    cudaLaunchAttribute attr[1];
    attr[0].id = cudaLaunchAttributeProgrammaticStreamSerialization;
    attr[0].val.programmaticStreamSerializationAllowed = 1;
    cfg.attrs = attr;
    cfg.numAttrs = 1;
    cudaLaunchKernelEx(&cfg, kern, args...);
}

// ---------------- launch ------------------------------------------------------
extern "C" void kernel_launch(void* const* d_in, const int* in_sizes, int n_in,
                              void* d_out, int out_size) {
    const float* x     = (const float*)d_in[0];
    const int*   ei    = (const int*)d_in[1];    // int32 (JAX x64 disabled)
    const int*   batch = (const int*)d_in[2];    // int32
    const float* W1    = (const float*)d_in[3];
    const float* b1    = (const float*)d_in[4];
    const float* gamma1= (const float*)d_in[5];
    const float* beta1 = (const float*)d_in[6];
    const float* W2    = (const float*)d_in[7];
    const float* b2    = (const float*)d_in[8];
    const float* Wc1   = (const float*)d_in[9];
    const float* bc1   = (const float*)d_in[10];
    const float* gammac= (const float*)d_in[11];
    const float* betac = (const float*)d_in[12];
    const float* Wc2   = (const float*)d_in[13];
    const float* bc2   = (const float*)d_in[14];

    float* out  = (float*)d_out;
    float* pred = out;              // [G, 10]
    float* rep  = out + GG * CC;    // [G, 64]

    const int nb_gemm = (NN + 127) / 128;    // 782

    pdl_launch(k_zero, dim3((NN + 255) / 256), dim3(256));
    pdl_launch(k_fill, dim3((EE / 4 + 255) / 256), dim3(256), ei);

    // conv1: tensor-core transform (+bucket pad) -> aggregate + sharded BN stats
    pdl_launch(k_gemm<0>, dim3(nb_gemm), dim3(256), x, W1, b1,
               (const float*)nullptr, (const float*)nullptr);
    pdl_launch(k_agg_bnstats, dim3(NN / 16), dim3(256));

    // conv2: BN(shard-reduced)+ReLU fused into transform -> aggregate + pooling
    pdl_launch(k_gemm<1>, dim3(nb_gemm), dim3(256), (const float*)nullptr, W2, b2,
               gamma1, beta1);
    pdl_launch(k_agg_pool, dim3(NN / 16), dim3(256), batch);

    // classifier
    pdl_launch(k_graph1, dim3((GG + 7) / 8), dim3(256), Wc1, bc1, rep);
    pdl_launch(k_graph2, dim3((GG + 7) / 8), dim3(256), Wc2, bc2, gammac, betac, pred);
}

// round 16
// speedup vs baseline: 1.1992x; 1.1992x over previous
#include <cuda_runtime.h>
#include <cuda_fp16.h>
#include <math.h>
#include <stdint.h>

#define NN 100000
#define EE 1600000
#define GG 1000
#define HH 64
#define CC 10
#define CAP 64      // per-node bucket capacity (deg ~ Poisson(16); P(>64) ~ 0)
#define BN_EPS 1e-5f
#define NSLOT 16    // BN stat shards (kills same-address REDG serialization)
#define SP 66       // padded smem row stride in halves (33 words -> conflict-free)

// ---------------- scratch (static device memory; no allocation at runtime) ----
__device__ __align__(16) int    g_cnt[NN];             // in-degree (excl self loop)
__device__ __align__(16) int    g_srcs[NN * CAP];      // bucketized CSR (padded to 4 with NN)
__device__ __align__(16) __half g_t[(NN + 1) * HH];    // dis-scaled features; row NN = zeros
__device__ __align__(16) float  g_h[NN * HH];          // conv1 output
__device__ __align__(16) float  g_bnp[NSLOT * 128];    // sharded BN sums
__device__ __align__(16) float  g_cbn[128];
__device__ __align__(16) float  g_gsum[GG * HH];
__device__ __align__(16) float  g_gcnt[GG];
__device__ __align__(16) float  g_z1[GG * HH];

// PDL: wait for upstream grid's memory to be visible
__device__ __forceinline__ void gds() {
#if defined(__CUDA_ARCH__) && __CUDA_ARCH__ >= 900
    cudaGridDependencySynchronize();
#endif
}

// ---------------- zero scratch ------------------------------------------------
__global__ void k_zero() {
    gds();   // don't race previous replay's tail kernels
    int i = blockIdx.x * blockDim.x + threadIdx.x;
    if (i < NN) g_cnt[i] = 0;
    if (i < NSLOT * 128) g_bnp[i] = 0.f;
    if (i < 128) g_cbn[i] = 0.f;
    if (i < GG * HH) g_gsum[i] = 0.f;
    if (i < GG) g_gcnt[i] = 0.f;
    if (i < 32) ((uint32_t*)g_t)[NN * 32 + i] = 0;   // sentinel row = zeros
}

// ------- single-pass bucket fill: 4 edges per thread (int4 loads) -------------
__global__ void k_fill(const int* __restrict__ ei) {
    int i = blockIdx.x * blockDim.x + threadIdx.x;
    if (i >= EE / 4) return;
    gds();
    int4 s = ((const int4*)ei)[i];
    int4 d = ((const int4*)(ei + EE))[i];
    int p;
    p = atomicAdd(&g_cnt[d.x], 1); if (p < CAP) g_srcs[d.x * CAP + p] = s.x;
    p = atomicAdd(&g_cnt[d.y], 1); if (p < CAP) g_srcs[d.y * CAP + p] = s.y;
    p = atomicAdd(&g_cnt[d.z], 1); if (p < CAP) g_srcs[d.z * CAP + p] = s.z;
    p = atomicAdd(&g_cnt[d.w], 1); if (p < CAP) g_srcs[d.w * CAP + p] = s.w;
}

// ---- tensor-core transform: g_t = dis[r] * ([BN+ReLU](src[r]) @ W + b) -------
// Also pads each covered bucket row to a multiple of 4 with sentinel NN.
template <int MODE>
__global__ void k_gemm(const float* __restrict__ in, const float* __restrict__ W,
                       const float* __restrict__ bias,
                       const float* __restrict__ gamma, const float* __restrict__ beta) {
    __shared__ __half xs[128 * SP];   // per-warp 16-row staging (fp16)
    __shared__ __half wt[64 * SP];    // W^T: wt[n][k]
    __shared__ float  bsh[64];
    __shared__ float  bnred[128];     // reduced BN sums (MODE 1)
    int tid = threadIdx.x;
    int warp = tid >> 5, lane = tid & 31;

    for (int i = tid; i < 4096; i += 256) {
        int n = i >> 6, k = i & 63;
        wt[n * SP + k] = __float2half(W[k * 64 + n]);
    }
    if (tid < 64) bsh[tid] = bias[tid];

    gds();   // upstream (fill / aggregate) results now visible

    // pad bucket rows to 4-multiple with sentinel (needs g_cnt from fill)
    if (tid < 128) {
        int pr = blockIdx.x * 128 + tid;
        if (pr < NN) {
            int d = g_cnt[pr];
            if (d < CAP) {
                int dp = (d + 3) & ~3;
                if (dp > CAP) dp = CAP;
                for (int j = d; j < dp; j++) g_srcs[pr * CAP + j] = NN;
            }
        }
    }

    // MODE 1: reduce the 16 BN shards into smem
    if (MODE == 1 && tid < 128) {
        float s = 0.f;
        #pragma unroll
        for (int j = 0; j < NSLOT; j++) s += g_bnp[j * 128 + tid];
        bnred[tid] = s;
    }
    __syncthreads();

    int c0 = 2 * lane, c1 = c0 + 1;
    float a0 = 1.f, s0 = 0.f, a1 = 1.f, s1 = 0.f;
    if (MODE == 1) {
        const float invn = 1.0f / NN;
        float mu0 = bnred[c0] * invn, mu1 = bnred[c1] * invn;
        float var0 = bnred[64 + c0] * invn - mu0 * mu0;
        float var1 = bnred[64 + c1] * invn - mu1 * mu1;
        a0 = rsqrtf(var0 + BN_EPS) * gamma[c0];
        a1 = rsqrtf(var1 + BN_EPS) * gamma[c1];
        s0 = beta[c0] - mu0 * a0;
        s1 = beta[c1] - mu1 * a1;
    }

    int wrow0 = blockIdx.x * 128 + warp * 16;   // NN % 16 == 0
    if (wrow0 >= NN) return;

    const float* __restrict__ src = (MODE == 1) ? (const float*)g_h : in;
    __half* xw = xs + warp * 16 * SP;

    #pragma unroll
    for (int r = 0; r < 16; r++) {
        float2 v = *(const float2*)(src + (size_t)(wrow0 + r) * 64 + c0);
        if (MODE == 1) {
            v.x = fmaxf(fmaf(v.x, a0, s0), 0.f);
            v.y = fmaxf(fmaf(v.y, a1, s1), 0.f);
        }
        *(__half2*)&xw[r * SP + c0] = __floats2half2_rn(v.x, v.y);
    }
    __syncwarp();

    int gr = lane >> 2, tg = lane & 3;
    float acc[8][4];
    #pragma unroll
    for (int nt = 0; nt < 8; nt++) {
        float bx = bsh[nt * 8 + tg * 2], by = bsh[nt * 8 + tg * 2 + 1];
        acc[nt][0] = bx; acc[nt][1] = by; acc[nt][2] = bx; acc[nt][3] = by;
    }
    #pragma unroll
    for (int ks = 0; ks < 4; ks++) {
        int kb = ks * 16 + tg * 2;
        uint32_t fa0 = *(const uint32_t*)&xw[gr * SP + kb];
        uint32_t fa1 = *(const uint32_t*)&xw[(gr + 8) * SP + kb];
        uint32_t fa2 = *(const uint32_t*)&xw[gr * SP + kb + 8];
        uint32_t fa3 = *(const uint32_t*)&xw[(gr + 8) * SP + kb + 8];
        #pragma unroll
        for (int nt = 0; nt < 8; nt++) {
            uint32_t fb0 = *(const uint32_t*)&wt[(nt * 8 + gr) * SP + kb];
            uint32_t fb1 = *(const uint32_t*)&wt[(nt * 8 + gr) * SP + kb + 8];
            asm volatile(
                "mma.sync.aligned.m16n8k16.row.col.f32.f16.f16.f32 "
                "{%0,%1,%2,%3}, {%4,%5,%6,%7}, {%8,%9}, {%0,%1,%2,%3};"
                : "+f"(acc[nt][0]), "+f"(acc[nt][1]), "+f"(acc[nt][2]), "+f"(acc[nt][3])
                : "r"(fa0), "r"(fa1), "r"(fa2), "r"(fa3), "r"(fb0), "r"(fb1));
        }
    }
    float dv0 = rsqrtf((float)(g_cnt[wrow0 + gr] + 1));
    float dv8 = rsqrtf((float)(g_cnt[wrow0 + gr + 8] + 1));
    __syncwarp();
    #pragma unroll
    for (int nt = 0; nt < 8; nt++) {
        int cc = nt * 8 + tg * 2;
        *(__half2*)&xw[gr * SP + cc]       = __floats2half2_rn(acc[nt][0] * dv0, acc[nt][1] * dv0);
        *(__half2*)&xw[(gr + 8) * SP + cc] = __floats2half2_rn(acc[nt][2] * dv8, acc[nt][3] * dv8);
    }
    __syncwarp();
    uint32_t* gw = (uint32_t*)g_t;
    #pragma unroll
    for (int r = 0; r < 16; r++) {
        gw[(size_t)(wrow0 + r) * 32 + lane] = ((const uint32_t*)&xw[r * SP])[lane];
    }
}

// ---- aggregate: quarter-warp scheme, 4 edges per LDG.128 ---------------------
// qt = lane>>3 owns edge e+qt; c8 = lane&7 owns cols [8*c8, 8*c8+8).
// Branch-free body, 2 fp16 accumulator sets (unroll 2), cross-quarter shfl_xor.
// After agg_node, EVERY lane holds the full 8-column result for its c8.
__device__ __forceinline__ void agg_node(int v, int lane, float f[8]) {
    int deg = g_cnt[v];
    int degp = (min(deg, CAP) + 3) & ~3;
    int qt = lane >> 3, c8 = lane & 7;
    const int* __restrict__ row = g_srcs + (size_t)v * CAP;
    const __half* __restrict__ t = g_t;
    __half2 z = __float2half2_rn(0.f);
    __half2 a0 = z, a1 = z, a2 = z, a3 = z;
    __half2 b0 = z, b1 = z, b2 = z, b3 = z;
    int e = 0;
    for (; e + 8 <= degp; e += 8) {
        int s0 = __ldg(row + e + qt);
        int s1 = __ldg(row + e + 4 + qt);
        uint4 u0 = __ldcg((const uint4*)(t + (size_t)s0 * 64) + c8);
        uint4 u1 = __ldcg((const uint4*)(t + (size_t)s1 * 64) + c8);
        a0 = __hadd2(a0, *(__half2*)&u0.x);
        a1 = __hadd2(a1, *(__half2*)&u0.y);
        a2 = __hadd2(a2, *(__half2*)&u0.z);
        a3 = __hadd2(a3, *(__half2*)&u0.w);
        b0 = __hadd2(b0, *(__half2*)&u1.x);
        b1 = __hadd2(b1, *(__half2*)&u1.y);
        b2 = __hadd2(b2, *(__half2*)&u1.z);
        b3 = __hadd2(b3, *(__half2*)&u1.w);
    }
    if (e < degp) {
        int s0 = __ldg(row + e + qt);
        uint4 u0 = __ldcg((const uint4*)(t + (size_t)s0 * 64) + c8);
        a0 = __hadd2(a0, *(__half2*)&u0.x);
        a1 = __hadd2(a1, *(__half2*)&u0.y);
        a2 = __hadd2(a2, *(__half2*)&u0.z);
        a3 = __hadd2(a3, *(__half2*)&u0.w);
    }
    // flush both fp16 sets to f32
    float2 p, q;
    p = __half22float2(a0); q = __half22float2(b0); f[0] = p.x + q.x; f[1] = p.y + q.y;
    p = __half22float2(a1); q = __half22float2(b1); f[2] = p.x + q.x; f[3] = p.y + q.y;
    p = __half22float2(a2); q = __half22float2(b2); f[4] = p.x + q.x; f[5] = p.y + q.y;
    p = __half22float2(a3); q = __half22float2(b3); f[6] = p.x + q.x; f[7] = p.y + q.y;
    // cross-quarter reduce (xor keeps every lane valid)
    #pragma unroll
    for (int j = 0; j < 8; j++) {
        f[j] += __shfl_xor_sync(0xffffffff, f[j], 8);
        f[j] += __shfl_xor_sync(0xffffffff, f[j], 16);
    }
    // self term + normalization
    uint4 us = __ldcg((const uint4*)(t + (size_t)v * 64) + c8);
    float2 s0 = __half22float2(*(__half2*)&us.x);
    float2 s1 = __half22float2(*(__half2*)&us.y);
    float2 s2 = __half22float2(*(__half2*)&us.z);
    float2 s3 = __half22float2(*(__half2*)&us.w);
    float dv = rsqrtf((float)(deg + 1));
    f[0] = (f[0] + s0.x) * dv;  f[1] = (f[1] + s0.y) * dv;
    f[2] = (f[2] + s1.x) * dv;  f[3] = (f[3] + s1.y) * dv;
    f[4] = (f[4] + s2.x) * dv;  f[5] = (f[5] + s2.y) * dv;
    f[6] = (f[6] + s3.x) * dv;  f[7] = (f[7] + s3.y) * dv;
}

// conv1 aggregate: 8 nodes/block, write g_h + sharded BN stats. NN%8==0.
__global__ void __launch_bounds__(256) k_agg_bnstats() {
    __shared__ __align__(16) float ssum[8][64];
    __shared__ __align__(16) float ssq[8][64];
    gds();
    int tid = threadIdx.x;
    int warp = tid >> 5, lane = tid & 31;
    int v = blockIdx.x * 8 + warp;
    float f[8];
    agg_node(v, lane, f);
    if (lane < 8) {
        float* hp = g_h + (size_t)v * 64 + lane * 8;
        *(float4*)hp       = make_float4(f[0], f[1], f[2], f[3]);
        *(float4*)(hp + 4) = make_float4(f[4], f[5], f[6], f[7]);
        *(float4*)&ssum[warp][lane * 8]     = make_float4(f[0], f[1], f[2], f[3]);
        *(float4*)&ssum[warp][lane * 8 + 4] = make_float4(f[4], f[5], f[6], f[7]);
        *(float4*)&ssq[warp][lane * 8]      = make_float4(f[0]*f[0], f[1]*f[1], f[2]*f[2], f[3]*f[3]);
        *(float4*)&ssq[warp][lane * 8 + 4]  = make_float4(f[4]*f[4], f[5]*f[5], f[6]*f[6], f[7]*f[7]);
    }
    __syncthreads();
    float* slot = g_bnp + (blockIdx.x & (NSLOT - 1)) * 128;
    if (tid < 64) {
        float s = 0.f, qq = 0.f;
        #pragma unroll
        for (int w = 0; w < 8; w++) { s += ssum[w][tid]; qq += ssq[w][tid]; }
        atomicAdd(&slot[tid], s);
        atomicAdd(&slot[64 + tid], qq);
    }
}

// conv2 aggregate fused with per-graph mean pooling (batch sorted -> run dedup)
__global__ void __launch_bounds__(256) k_agg_pool(const int* __restrict__ batch) {
    __shared__ __align__(16) float vals[8][64];
    __shared__ int gids[8];
    gds();
    int tid = threadIdx.x;
    int warp = tid >> 5, lane = tid & 31;
    int v = blockIdx.x * 8 + warp;
    float f[8];
    agg_node(v, lane, f);
    if (lane < 8) {
        *(float4*)&vals[warp][lane * 8]     = make_float4(f[0], f[1], f[2], f[3]);
        *(float4*)&vals[warp][lane * 8 + 4] = make_float4(f[4], f[5], f[6], f[7]);
    }
    if (lane == 0) gids[warp] = batch[v];
    __syncthreads();
    if (tid < 64) {
        int c = tid;
        float acc = 0.f;
        int cur = -1;
        #pragma unroll
        for (int w = 0; w < 8; w++) {
            int gw = gids[w];
            if (gw != cur) {
                if (cur >= 0) atomicAdd(&g_gsum[cur * 64 + c], acc);
                cur = gw;
                acc = 0.f;
            }
            acc += vals[w][c];
        }
        if (cur >= 0) atomicAdd(&g_gsum[cur * 64 + c], acc);
    } else if (tid == 64) {
        float cnt = 0.f;
        int cur = -1;
        #pragma unroll
        for (int w = 0; w < 8; w++) {
            int gw = gids[w];
            if (gw != cur) {
                if (cur >= 0) atomicAdd(&g_gcnt[cur], cnt);
                cur = gw;
                cnt = 0.f;
            }
            cnt += 1.f;
        }
        if (cur >= 0) atomicAdd(&g_gcnt[cur], cnt);
    }
}

// ---------------- graph-level: pool finalize + L2 norm + Wc1 ------------------
__global__ void k_graph1(const float* __restrict__ Wc1, const float* __restrict__ bc1,
                         float* __restrict__ rep_out) {
    __shared__ __align__(16) float Wsh[64 * 64];
    __shared__ float bsh[64];
    __shared__ float xsh[8][64];
    int tid = threadIdx.x;
    for (int i = tid; i < 4096; i += 256) Wsh[i] = Wc1[i];
    if (tid < 64) bsh[tid] = bc1[tid];
    gds();
    __syncthreads();
    int warp = tid >> 5, lane = tid & 31;
    int g = blockIdx.x * 8 + warp;
    if (g >= GG) return;
    float cnt = fmaxf(g_gcnt[g], 1.0f);
    float mx = g_gsum[g * 64 + 2 * lane] / cnt;
    float my = g_gsum[g * 64 + 2 * lane + 1] / cnt;
    float ss = mx * mx + my * my;
    #pragma unroll
    for (int o = 16; o > 0; o >>= 1) ss += __shfl_xor_sync(0xffffffff, ss, o);
    float inv = rsqrtf(ss);
    mx *= inv; my *= inv;
    rep_out[g * 64 + 2 * lane] = mx;
    rep_out[g * 64 + 2 * lane + 1] = my;
    xsh[warp][2 * lane] = mx;
    xsh[warp][2 * lane + 1] = my;
    __syncwarp();
    float ax = bsh[2 * lane], ay = bsh[2 * lane + 1];
    #pragma unroll
    for (int k = 0; k < 64; k++) {
        float xk = xsh[warp][k];
        float2 w = *(const float2*)&Wsh[k * 64 + 2 * lane];
        ax += xk * w.x;
        ay += xk * w.y;
    }
    g_z1[g * 64 + 2 * lane] = ax;
    g_z1[g * 64 + 2 * lane + 1] = ay;
    atomicAdd(&g_cbn[2 * lane], ax);
    atomicAdd(&g_cbn[2 * lane + 1], ay);
    atomicAdd(&g_cbn[64 + 2 * lane], ax * ax);
    atomicAdd(&g_cbn[64 + 2 * lane + 1], ay * ay);
}

// ---- classifier tail: BN(finalized in-kernel)+ReLU -> Wc2 -> log_softmax -----
__global__ void k_graph2(const float* __restrict__ Wc2, const float* __restrict__ bc2,
                         const float* __restrict__ gammac, const float* __restrict__ betac,
                         float* __restrict__ pred_out) {
    __shared__ float Wsh[64 * 10];
    __shared__ float xsh[8][64];
    int tid = threadIdx.x;
    for (int i = tid; i < 640; i += 256) Wsh[i] = Wc2[i];
    gds();
    __syncthreads();
    int warp = tid >> 5, lane = tid & 31;
    int g = blockIdx.x * 8 + warp;
    if (g >= GG) return;
    int c0 = 2 * lane, c1 = 2 * lane + 1;
    const float invg = 1.0f / GG;
    float mu0 = g_cbn[c0] * invg, mu1 = g_cbn[c1] * invg;
    float var0 = g_cbn[64 + c0] * invg - mu0 * mu0;
    float var1 = g_cbn[64 + c1] * invg - mu1 * mu1;
    float is0 = rsqrtf(var0 + BN_EPS), is1 = rsqrtf(var1 + BN_EPS);
    float z0 = g_z1[g * 64 + c0];
    float z1v = g_z1[g * 64 + c1];
    z0 = fmaxf((z0 - mu0) * is0 * gammac[c0] + betac[c0], 0.f);
    z1v = fmaxf((z1v - mu1) * is1 * gammac[c1] + betac[c1], 0.f);
    xsh[warp][c0] = z0;
    xsh[warp][c1] = z1v;
    __syncwarp();
    bool valid = (lane < CC);
    float acc = valid ? bc2[lane] : 0.f;
    if (valid) {
        #pragma unroll
        for (int k = 0; k < 64; k++) acc += xsh[warp][k] * Wsh[k * 10 + lane];
    }
    float v = valid ? acc : -1e30f;
    float m = v;
    #pragma unroll
    for (int o = 16; o > 0; o >>= 1) m = fmaxf(m, __shfl_xor_sync(0xffffffff, m, o));
    float ex = valid ? __expf(v - m) : 0.f;
    float s = ex;
    #pragma unroll
    for (int o = 16; o > 0; o >>= 1) s += __shfl_xor_sync(0xffffffff, s, o);
    if (valid) pred_out[g * CC + lane] = v - m - logf(s);
}

// ---------------- PDL launcher ------------------------------------------------
template <typename... Args>
static inline void pdl_launch(void (*kern)(Args...), dim3 grid, dim3 block, Args... args) {
    cudaLaunchConfig_t cfg = {};
    cfg.gridDim = grid;
    cfg.blockDim = block;
    cfg.dynamicSmemBytes = 0;
    cfg.stream = 0;
    cudaLaunchAttribute attr[1];
    attr[0].id = cudaLaunchAttributeProgrammaticStreamSerialization;
    attr[0].val.programmaticStreamSerializationAllowed = 1;
    cfg.attrs = attr;
    cfg.numAttrs = 1;
    cudaLaunchKernelEx(&cfg, kern, args...);
}

// ---------------- launch ------------------------------------------------------
extern "C" void kernel_launch(void* const* d_in, const int* in_sizes, int n_in,
                              void* d_out, int out_size) {
    const float* x     = (const float*)d_in[0];
    const int*   ei    = (const int*)d_in[1];    // int32 (JAX x64 disabled)
    const int*   batch = (const int*)d_in[2];    // int32
    const float* W1    = (const float*)d_in[3];
    const float* b1    = (const float*)d_in[4];
    const float* gamma1= (const float*)d_in[5];
    const float* beta1 = (const float*)d_in[6];
    const float* W2    = (const float*)d_in[7];
    const float* b2    = (const float*)d_in[8];
    const float* Wc1   = (const float*)d_in[9];
    const float* bc1   = (const float*)d_in[10];
    const float* gammac= (const float*)d_in[11];
    const float* betac = (const float*)d_in[12];
    const float* Wc2   = (const float*)d_in[13];
    const float* bc2   = (const float*)d_in[14];

    float* out  = (float*)d_out;
    float* pred = out;              // [G, 10]
    float* rep  = out + GG * CC;    // [G, 64]

    const int nb_gemm = (NN + 127) / 128;    // 782

    pdl_launch(k_zero, dim3((NN + 255) / 256), dim3(256));
    pdl_launch(k_fill, dim3((EE / 4 + 255) / 256), dim3(256), ei);

    // conv1: tensor-core transform (+bucket pad) -> aggregate + sharded BN stats
    pdl_launch(k_gemm<0>, dim3(nb_gemm), dim3(256), x, W1, b1,
               (const float*)nullptr, (const float*)nullptr);
    pdl_launch(k_agg_bnstats, dim3(NN / 8), dim3(256));

    // conv2: BN(shard-reduced)+ReLU fused into transform -> aggregate + pooling
    pdl_launch(k_gemm<1>, dim3(nb_gemm), dim3(256), (const float*)nullptr, W2, b2,
               gamma1, beta1);
    pdl_launch(k_agg_pool, dim3(NN / 8), dim3(256), batch);

    // classifier
    pdl_launch(k_graph1, dim3((GG + 7) / 8), dim3(256), Wc1, bc1, rep);
    pdl_launch(k_graph2, dim3((GG + 7) / 8), dim3(256), Wc2, bc2, gammac, betac, pred);
}